// round 16
// baseline (speedup 1.0000x reference)
#include <cuda_runtime.h>
#include <math.h>

#define NN 20000
#define EE 320000
#define CC 64
#define ZZ 10
#define LLAYERS 2
#define HH 64
#define NBES 8
#define TT 1024
#define NBINS (TT-1)

typedef unsigned long long ull;

// ---------------- scratch (device globals; no allocation allowed) ----------------
__device__ float  g_s[NN*CC];
__device__ float  g_v[NN*3*CC];
__device__ float4 g_up[NN*CC];                 // (s_up, vx, vy, vz)
__device__ float4 g_agg[NN*CC];                // (agg0, a1x, a1y, a1z)
__device__ float4 g_tab4[LLAYERS][TT*CC];      // (w00, w110/√3, w011, w101) * 1/32
__device__ float  g_tab1[LLAYERS][TT*CC];      // w111/√2 * 1/32
// unsorted per-edge geometry cache
__device__ int    g_ebinU[EE];
__device__ float4 g_eyfU[EE];
// edge bins (by table row)  -- counters zeroed by trailing cleanup kernel
__device__ int    g_bcnt[NBINS];
__device__ int    g_brow[NBINS+1];
__device__ int    g_bwo[NBINS];
__device__ int2   g_esr[EE];                   // (sender, receiver)
__device__ float4 g_eyf[EE];                   // (y0, y1, y2, f)
// node z-sort
__device__ int    g_zcnt[ZZ];
__device__ int    g_zrow[ZZ+1];
__device__ int    g_zwo[ZZ];
__device__ int    g_nid[NN];
__device__ int    g_zU[NN];

__device__ __forceinline__ float silu_f(float x){ return x * (1.0f/(1.0f + __expf(-x))); }

// ---------------- f32x2 helpers ----------------
__device__ __forceinline__ ull pk2(float x){
    ull r; asm("mov.b64 %0, {%1, %1};" : "=l"(r) : "f"(x)); return r;
}
__device__ __forceinline__ void upk(ull p, float& lo, float& hi){
    asm("mov.b64 {%0, %1}, %2;" : "=f"(lo), "=f"(hi) : "l"(p));
}
__device__ __forceinline__ void fma2(ull& d, ull a, ull b){
    asm("fma.rn.f32x2 %0, %1, %2, %0;" : "+l"(d) : "l"(a), "l"(b));
}

// ---------------- fused: edge hist + node z-hist + embedding ----------------
#define EBLK ((EE+255)/256)
#define NBLK ((NN+255)/256)
#define SBLK ((NN*CC+255)/256)

__global__ void k_hist_all(const float* __restrict__ pos, const float* __restrict__ shifts,
                           const int* __restrict__ eidx, const float* __restrict__ attrs,
                           const float* __restrict__ Wemb)
{
    if (blockIdx.x < EBLK) {
        int e = blockIdx.x*blockDim.x + threadIdx.x;
        if (e >= EE) return;
        int snd = eidx[e], rcv = eidx[EE + e];
        float vx = pos[rcv*3+0]-pos[snd*3+0]+shifts[e*3+0];
        float vy = pos[rcv*3+1]-pos[snd*3+1]+shifts[e*3+1];
        float vz = pos[rcv*3+2]-pos[snd*3+2]+shifts[e*3+2];
        float r = sqrtf(vx*vx+vy*vy+vz*vz);
        float u = r * 0.2f;
        if (u >= 1.0f) { g_ebinU[e] = -1; return; }
        float t = u * (float)(TT-1);
        int i0 = (int)t; if (i0 > NBINS-1) i0 = NBINS-1;
        float f = t - (float)i0;
        float inv = 1.0f/(r + 1e-9f);
        const float S3 = 1.7320508075688772f;
        g_ebinU[e] = i0;
        g_eyfU[e]  = make_float4(S3*vx*inv, S3*vy*inv, S3*vz*inv, f);
        atomicAdd(&g_bcnt[i0], 1);
    } else if (blockIdx.x < EBLK + NBLK) {
        int n = (blockIdx.x - EBLK)*blockDim.x + threadIdx.x;
        if (n >= NN) return;
        int z = 0;
        #pragma unroll
        for (int j=0;j<ZZ;j++) if (__ldg(attrs + n*ZZ + j) > 0.5f) z = j;
        g_zU[n] = z;
        atomicAdd(&g_zcnt[z], 1);
    } else {
        int idx = (blockIdx.x - EBLK - NBLK)*blockDim.x + threadIdx.x;
        if (idx >= NN*CC) return;
        int n = idx >> 6, c = idx & 63;
        float acc = 0.f;
        #pragma unroll
        for (int z=0; z<ZZ; z++) acc += __ldg(attrs + n*ZZ + z) * __ldg(Wemb + z*CC + c);
        g_s[idx] = acc;
        g_v[n*192 + c]       = 0.f;
        g_v[n*192 + 64 + c]  = 0.f;
        g_v[n*192 + 128 + c] = 0.f;
    }
}

// ---------------- scans (2 independent blocks) ----------------
__global__ void k_scans()
{
    __shared__ int partial[1024];
    int tid = threadIdx.x;
    if (blockIdx.x == 0) {          // bin scan (NBINS=1023 <= 1024)
        int sum = (tid < NBINS) ? g_bcnt[tid] : 0;
        partial[tid] = sum;
        __syncthreads();
        for (int off=1; off<1024; off<<=1){
            int v = (tid>=off) ? partial[tid-off] : 0;
            __syncthreads();
            partial[tid] += v;
            __syncthreads();
        }
        int run = (tid==0) ? 0 : partial[tid-1];
        if (tid == 1023) g_brow[NBINS] = partial[1023];
        if (tid < NBINS){
            g_brow[tid] = run;
            g_bwo[tid]  = run;
        }
    } else {
        if (tid == 0){
            int run = 0;
            for (int z=0; z<ZZ; z++){
                g_zrow[z] = run; g_zwo[z] = run;
                run += g_zcnt[z];
            }
            g_zrow[ZZ] = run;
        }
    }
}

// ---------------- fused scatter: edges into bin order + nodes into z order ----------------
__global__ void k_scatter_all(const int* __restrict__ eidx)
{
    if (blockIdx.x < EBLK) {
        int e = blockIdx.x*blockDim.x + threadIdx.x;
        if (e >= EE) return;
        int b = g_ebinU[e];
        if (b < 0) return;
        int p = atomicAdd(&g_bwo[b], 1);
        g_esr[p] = make_int2(eidx[e], eidx[EE+e]);
        g_eyf[p] = g_eyfU[e];
    } else {
        int n = (blockIdx.x - EBLK)*blockDim.x + threadIdx.x;
        if (n >= NN) return;
        int p = atomicAdd(&g_zwo[g_zU[n]], 1);
        g_nid[p] = n;
    }
}

// ---------------- trailing cleanup: leave counters zeroed for the next call ----------------
__global__ void k_cleanup()
{
    int i = blockIdx.x*blockDim.x + threadIdx.x;
    if (i < NBINS) g_bcnt[i] = 0;
    if (i < ZZ)    g_zcnt[i] = 0;
}

// ---------------- radial MLP table: smem weights (float4 staged), 16 rows/block ----------------
#define TROWS 16
#define TBL_SMEM_BYTES ((NBES*HH + HH*HH + HH*5*CC + 4*(NBES+HH+HH))*4)

__device__ __forceinline__ void grp_bar(int grp){
    asm volatile("bar.sync %0, 64;" :: "r"(1+grp) : "memory");
}

__global__ __launch_bounds__(256) void k_table(const float* __restrict__ RW1,
                                               const float* __restrict__ RW2,
                                               const float* __restrict__ RW3)
{
    int l = blockIdx.y;
    extern __shared__ float sm[];
    float* sW1 = sm;                      // 512
    float* sW2 = sW1 + NBES*HH;           // 4096
    float* sW3 = sW2 + HH*HH;             // 20480
    float* sFt = sW3 + HH*5*CC;           // 4*8
    float* sH1 = sFt + 4*NBES;            // 4*64
    float* sH2 = sH1 + 4*HH;              // 4*64
    const float4* W1v = (const float4*)(RW1 + l*NBES*HH);
    const float4* W2v = (const float4*)(RW2 + l*HH*HH);
    const float4* W3v = (const float4*)(RW3 + l*HH*5*CC);
    int tid = threadIdx.x;
    for (int i=tid;i<(NBES*HH)/4;i+=256) ((float4*)sW1)[i]=__ldg(W1v+i);
    for (int i=tid;i<(HH*HH)/4;  i+=256) ((float4*)sW2)[i]=__ldg(W2v+i);
    for (int i=tid;i<(HH*5*CC)/4;i+=256) ((float4*)sW3)[i]=__ldg(W3v+i);
    __syncthreads();

    int grp = tid >> 6;      // 0..3 (independent row pipelines)
    int gt  = tid & 63;      // channel within group
    const float PI = 3.14159265358979323846f;
    const float IA  = 1.0f/32.0f;
    const float IS3 = 0.5773502691896258f;
    const float IS2 = 0.7071067811865475f;

    for (int r = grp; r < TROWS; r += 4) {
        int i = blockIdx.x*TROWS + r;
        if (gt < NBES) {
            float u = (float)i / (float)(TT-1);
            float rr = 5.0f*u;
            float inv = 1.0f/(rr + 1e-9f);
            float env = 0.0f;
            if (u < 1.0f) {
                float u2=u*u, u4=u2*u2, u6=u4*u2;
                env = 1.0f - 28.0f*u6 + 48.0f*u6*u - 21.0f*u6*u2;
            }
            float pref = 0.6324555320336759f * inv * env;
            sFt[grp*NBES + gt] = pref * sinf((float)(gt+1) * PI * u);
        }
        grp_bar(grp);
        {
            float a = 0.f;
            #pragma unroll
            for (int k=0;k<NBES;k++) a += sFt[grp*NBES+k]*sW1[k*HH+gt];
            sH1[grp*HH+gt] = silu_f(a);
        }
        grp_bar(grp);
        {
            float a = 0.f;
            #pragma unroll 8
            for (int d=0;d<HH;d++) a += sH1[grp*HH+d]*sW2[d*HH+gt];
            sH2[grp*HH+gt] = silu_f(a);
        }
        grp_bar(grp);
        {
            float o[5] = {};
            #pragma unroll 8
            for (int d=0;d<HH;d++){
                float h = sH2[grp*HH+d];
                #pragma unroll
                for (int g=0;g<5;g++) o[g] += h*sW3[d*320 + g*64 + gt];
            }
            g_tab4[l][i*64 + gt] = make_float4(o[0]*IA, o[1]*IA*IS3, o[2]*IA, o[3]*IA);
            g_tab1[l][i*64 + gt] = o[4]*IA*IS2;
        }
        grp_bar(grp);
    }
}

// ---------------- s_up / v_up: f32x2 packed, paired weights, 2 nodes/warp + agg zero ----------------
#define UP_SMEM_BYTES (2*CC*CC*4 + 8*2*CC*16)

__global__ __launch_bounds__(256) void k_up(const float* __restrict__ Ws, const float* __restrict__ Wv)
{
    extern __shared__ float sm[];
    float*  sWs = sm;
    float*  sWv = sm + 4096;
    float4* stage = (float4*)(sm + 8192);
    int tid = threadIdx.x;
    // paired layout: channel pair (l, l+32) adjacent
    for (int i=tid;i<4096;i+=256){
        int c = i>>6, l = i&63;
        int dst = (c<<6) | ((l<32) ? (l<<1) : (((l-32)<<1)|1));
        sWs[dst]=Ws[i]; sWv[dst]=Wv[i];
    }
    __syncthreads();
    int warp = tid>>5, lane = tid&31;
    int n0 = (blockIdx.x*8 + warp)*2;
    if (n0 >= NN) return;
    int nk = (n0+1 < NN) ? 2 : 1;
    float4* st = stage + warp*2*CC;
    const ull* ws8 = (const ull*)sWs;
    const ull* wv8 = (const ull*)sWv;
    float4 z4 = make_float4(0.f,0.f,0.f,0.f);
    for (int t=0;t<nk;t++){
        int n = n0 + t;
        st[t*CC+lane]    = make_float4(g_s[n*64+lane],
                                       g_v[n*192+lane], g_v[n*192+64+lane], g_v[n*192+128+lane]);
        st[t*CC+lane+32] = make_float4(g_s[n*64+lane+32],
                                       g_v[n*192+lane+32], g_v[n*192+64+lane+32], g_v[n*192+128+lane+32]);
        g_agg[n*64+lane]    = z4;
        g_agg[n*64+lane+32] = z4;
    }
    if (nk < 2){ st[CC+lane]=z4; st[CC+lane+32]=z4; }
    __syncwarp();
    ull as[2]={0,0}, av[2][3]={{0,0,0},{0,0,0}};
    #pragma unroll 4
    for (int c=0;c<CC;c++){
        int wi = (c<<5) + lane;
        ull ws = ws8[wi], wv = wv8[wi];
        #pragma unroll
        for (int t=0;t<2;t++){
            float4 sv = st[t*CC+c];
            fma2(as[t],    pk2(sv.x), ws);
            fma2(av[t][0], pk2(sv.y), wv);
            fma2(av[t][1], pk2(sv.z), wv);
            fma2(av[t][2], pk2(sv.w), wv);
        }
    }
    for (int t=0;t<nk;t++){
        int n = n0 + t;
        float a0,a1, x0,x1, y0,y1, zz0,zz1;
        upk(as[t], a0, a1);
        upk(av[t][0], x0, x1);
        upk(av[t][1], y0, y1);
        upk(av[t][2], zz0, zz1);
        g_up[n*64+lane]    = make_float4(a0, x0, y0, zz0);
        g_up[n*64+lane+32] = make_float4(a1, x1, y1, zz1);
    }
}

// ---------------- edge kernel: block per u-bin, 16 warps, 2-edge ILP + record prefetch ----------------
__device__ __forceinline__ void edge_emit(int rcv, float4 yf, float4 up, int c,
    const float4* sA4, const float4* sD4, const float* sA1, const float* sD1)
{
    float f = yf.w;
    float4 a4 = sA4[c], d4 = sD4[c];
    float w0 = fmaf(f, d4.x, a4.x);
    float w1 = fmaf(f, d4.y, a4.y);
    float w2 = fmaf(f, d4.z, a4.z);
    float w3 = fmaf(f, d4.w, a4.w);
    float w4 = fmaf(f, sD1[c], sA1[c]);
    float dv = up.y*yf.x + up.z*yf.y + up.w*yf.z;
    float m0 = w0*up.x + w1*dv;
    float cx = up.z*yf.z - up.w*yf.y;
    float cy = up.w*yf.x - up.y*yf.z;
    float cz = up.y*yf.y - up.z*yf.x;
    float sy = w2*up.x;
    float m1x = sy*yf.x + w3*up.y + w4*cx;
    float m1y = sy*yf.y + w3*up.z + w4*cy;
    float m1z = sy*yf.z + w3*up.w + w4*cz;
    float* p = (float*)(g_agg + rcv*64 + c);
    asm volatile("red.global.add.v4.f32 [%0], {%1,%2,%3,%4};"
                 :: "l"(p), "f"(m0), "f"(m1x), "f"(m1y), "f"(m1z) : "memory");
}

__global__ __launch_bounds__(512) void k_edge(int layer)
{
    __shared__ float4 sA4[CC], sD4[CC];
    __shared__ float  sA1[CC], sD1[CC];
    int bin = blockIdx.x;
    int s0 = __ldg(&g_brow[bin]);
    int s1 = __ldg(&g_brow[bin+1]);
    if (s0 == s1) return;
    int tid = threadIdx.x;
    if (tid < CC) {
        float4 a4 = g_tab4[layer][bin*CC + tid];
        float4 b4 = g_tab4[layer][(bin+1)*CC + tid];
        sA4[tid] = a4;
        sD4[tid] = make_float4(b4.x-a4.x, b4.y-a4.y, b4.z-a4.z, b4.w-a4.w);
        float a1 = g_tab1[layer][bin*CC + tid];
        float b1 = g_tab1[layer][(bin+1)*CC + tid];
        sA1[tid] = a1; sD1[tid] = b1 - a1;
    }
    __syncthreads();
    int warp = tid>>5, lane = tid&31;

    // software pipeline: records for iteration i prefetched during iteration i-1
    int j = s0 + warp*2;
    bool hA = (j < s1), hB = (j+1 < s1);
    int2 srA, srB; float4 yfA, yfB;
    if (hA){ srA = __ldg(&g_esr[j]);   yfA = __ldg(&g_eyf[j]); }
    if (hB){ srB = __ldg(&g_esr[j+1]); yfB = __ldg(&g_eyf[j+1]); }

    while (hA) {
        // gathers for current iteration issue immediately (records already resident)
        float4 uA0 = __ldg(&g_up[srA.x*64 + lane]);
        float4 uA1 = __ldg(&g_up[srA.x*64 + lane + 32]);
        float4 uB0, uB1;
        if (hB){
            uB0 = __ldg(&g_up[srB.x*64 + lane]);
            uB1 = __ldg(&g_up[srB.x*64 + lane + 32]);
        }
        // prefetch next iteration's records (overlaps with gathers + compute below)
        int jn = j + 32;
        bool hA2 = (jn < s1), hB2 = (jn+1 < s1);
        int2 srA2, srB2; float4 yfA2, yfB2;
        if (hA2){ srA2 = __ldg(&g_esr[jn]);   yfA2 = __ldg(&g_eyf[jn]); }
        if (hB2){ srB2 = __ldg(&g_esr[jn+1]); yfB2 = __ldg(&g_eyf[jn+1]); }

        edge_emit(srA.y, yfA, uA0, lane,      sA4, sD4, sA1, sD1);
        edge_emit(srA.y, yfA, uA1, lane + 32, sA4, sD4, sA1, sD1);
        if (hB){
            edge_emit(srB.y, yfB, uB0, lane,      sA4, sD4, sA1, sD1);
            edge_emit(srB.y, yfB, uB1, lane + 32, sA4, sD4, sA1, sD1);
        }

        srA = srA2; yfA = yfA2; srB = srB2; yfB = yfB2;
        hA = hA2; hB = hB2; j = jn;
    }
}

// ---------------- node update: f32x2 packed math; LAST skips dead v-path ----------------
#define NODE_SMEM_FLOATS (6*CC*CC + 8*3*CC*4)
#define NODE_GX 32

template<bool LAST>
__global__ __launch_bounds__(256) void k_node(
    const float* __restrict__ Wout_s, const float* __restrict__ Wout_v,
    const float* __restrict__ Wsc_sL, const float* __restrict__ Wsc_vL,
    const float* __restrict__ P0L,    const float* __restrict__ P1L,
    const float* __restrict__ Wprod_s,const float* __restrict__ Wprod_v,
    float* __restrict__ outL)
{
    int z  = blockIdx.y;
    int s0 = g_zrow[z];
    int s1 = g_zrow[z+1];
    if (s0 + (int)blockIdx.x*8 >= s1) return;

    extern __shared__ float sm[];
    float* sWos = sm;
    float* sWov = sWos + 4096;
    float* sWss = sWov + 4096;
    float* sWsv = sWss + 4096;
    float* sWps = sWsv + 4096;
    float* sWpv = sWps + 4096;
    float4* stage = (float4*)(sm + 6*4096);
    int tid = threadIdx.x;
    const float* Wss_g = Wsc_sL + (size_t)z*4096;
    const float* Wsv_g = Wsc_vL + (size_t)z*4096;
    for (int i=tid;i<4096;i+=blockDim.x){
        int c = i>>6, l = i&63;
        int dst = (c<<6) | ((l<32) ? (l<<1) : (((l-32)<<1)|1));
        sWos[dst]=Wout_s[i]; sWov[dst]=Wout_v[i];
        sWss[dst]=__ldg(Wss_g+i);
        sWps[dst]=Wprod_s[i];
        if (!LAST){ sWsv[dst]=__ldg(Wsv_g+i); sWpv[dst]=Wprod_v[i]; }
    }
    __syncthreads();
    int warp = tid>>5, lane = tid&31;
    float4* stA = stage + warp*3*CC;   // agg  [64]
    float4* stS = stA + CC;            // (s, v) [64]
    float4* stP = stS + CC;            // prod [64]
    const ull* wos8 = (const ull*)sWos;
    const ull* wov8 = (const ull*)sWov;
    const ull* wss8 = (const ull*)sWss;
    const ull* wsv8 = (const ull*)sWsv;
    const ull* wps8 = (const ull*)sWps;
    const ull* wpv8 = (const ull*)sWpv;

    const float* p0  = P0L + (size_t)z*CC*3;
    const float* q0  = P1L + (size_t)z*CC*2;
    float pa0=__ldg(p0+lane*3+0), pa1=__ldg(p0+lane*3+1), pa2=__ldg(p0+lane*3+2);
    float pb0=__ldg(p0+(lane+32)*3+0), pb1=__ldg(p0+(lane+32)*3+1), pb2=__ldg(p0+(lane+32)*3+2);
    float qa0=__ldg(q0+lane*2+0), qa1=__ldg(q0+lane*2+1);
    float qb0=__ldg(q0+(lane+32)*2+0), qb1=__ldg(q0+(lane+32)*2+1);

    for (int idx = s0 + blockIdx.x*8 + warp; idx < s1; idx += NODE_GX*8) {
        int n = __ldg(&g_nid[idx]);

        stA[lane]    = g_agg[n*64+lane];
        stA[lane+32] = g_agg[n*64+lane+32];
        stS[lane]    = make_float4(g_s[n*64+lane],
                                   g_v[n*192+lane], g_v[n*192+64+lane], g_v[n*192+128+lane]);
        stS[lane+32] = make_float4(g_s[n*64+lane+32],
                                   g_v[n*192+lane+32], g_v[n*192+64+lane+32], g_v[n*192+128+lane+32]);
        __syncwarp();

        ull ms = 0, scs = 0;
        ull mv0=0, mv1=0, mv2=0, scv0=0, scv1=0, scv2=0;
        #pragma unroll 4
        for (int c=0;c<CC;c++){
            float4 A = stA[c];
            float4 S = stS[c];
            int wi = (c<<5) + lane;
            fma2(ms,  pk2(A.x), wos8[wi]);
            fma2(scs, pk2(S.x), wss8[wi]);
            ull wov = wov8[wi];
            fma2(mv0, pk2(A.y), wov);
            fma2(mv1, pk2(A.z), wov);
            fma2(mv2, pk2(A.w), wov);
            if (!LAST){
                ull wsv = wsv8[wi];
                fma2(scv0, pk2(S.y), wsv);
                fma2(scv1, pk2(S.z), wsv);
                fma2(scv2, pk2(S.w), wsv);
            }
        }

        float ms0, ms1, mvx0,mvx1, mvy0,mvy1, mvz0,mvz1;
        upk(ms, ms0, ms1);
        upk(mv0, mvx0, mvx1);
        upk(mv1, mvy0, mvy1);
        upk(mv2, mvz0, mvz1);

        float n2a = mvx0*mvx0 + mvy0*mvy0 + mvz0*mvz0;
        float n2b = mvx1*mvx1 + mvy1*mvy1 + mvz1*mvz1;
        float ga = qa0 + qa1*ms0;
        float gb = qb0 + qb1*ms1;
        stP[lane]    = make_float4(pa0*ms0 + pa1*ms0*ms0 + pa2*n2a, ga*mvx0, ga*mvy0, ga*mvz0);
        stP[lane+32] = make_float4(pb0*ms1 + pb1*ms1*ms1 + pb2*n2b, gb*mvx1, gb*mvy1, gb*mvz1);
        __syncwarp();

        ull sn = scs, vn0 = scv0, vn1 = scv1, vn2 = scv2;
        #pragma unroll 4
        for (int c=0;c<CC;c++){
            float4 P = stP[c];
            int wi = (c<<5) + lane;
            fma2(sn,  pk2(P.x), wps8[wi]);
            if (!LAST){
                ull wpv = wpv8[wi];
                fma2(vn0, pk2(P.y), wpv);
                fma2(vn1, pk2(P.z), wpv);
                fma2(vn2, pk2(P.w), wpv);
            }
        }

        float sn0,sn1;
        upk(sn, sn0, sn1);
        if (!LAST){
            float vx0,vx1, vy0,vy1, vz0,vz1;
            upk(vn0, vx0, vx1);
            upk(vn1, vy0, vy1);
            upk(vn2, vz0, vz1);
            g_s[n*64+lane]=sn0; g_s[n*64+lane+32]=sn1;
            g_v[n*192+lane]=vx0;      g_v[n*192+lane+32]=vx1;
            g_v[n*192+64+lane]=vy0;   g_v[n*192+64+lane+32]=vy1;
            g_v[n*192+128+lane]=vz0;  g_v[n*192+128+lane+32]=vz1;
        }
        outL[n*128+lane]=sn0; outL[n*128+lane+32]=sn1;
        __syncwarp();
    }
}

// ---------------- launch ----------------
extern "C" void kernel_launch(void* const* d_in, const int* in_sizes, int n_in,
                              void* d_out, int out_size)
{
    const float* attrs   = (const float*)d_in[0];
    const float* pos     = (const float*)d_in[1];
    const float* shifts  = (const float*)d_in[2];
    const float* Wemb    = (const float*)d_in[3];
    const float* Wup_s   = (const float*)d_in[4];
    const float* Wup_v   = (const float*)d_in[5];
    const float* RW1     = (const float*)d_in[6];
    const float* RW2     = (const float*)d_in[7];
    const float* RW3     = (const float*)d_in[8];
    const float* Wout_s  = (const float*)d_in[9];
    const float* Wout_v  = (const float*)d_in[10];
    const float* Wsc_s   = (const float*)d_in[11];
    const float* Wsc_v   = (const float*)d_in[12];
    const float* P0      = (const float*)d_in[13];
    const float* P1      = (const float*)d_in[14];
    const float* Wprod_s = (const float*)d_in[15];
    const float* Wprod_v = (const float*)d_in[16];
    const int*   eidx    = (const int*)d_in[17];
    float* out = (float*)d_out;

    const int node_smem = NODE_SMEM_FLOATS * 4;
    cudaFuncSetAttribute(k_up, cudaFuncAttributeMaxDynamicSharedMemorySize, UP_SMEM_BYTES);
    cudaFuncSetAttribute(k_table, cudaFuncAttributeMaxDynamicSharedMemorySize, TBL_SMEM_BYTES);
    cudaFuncSetAttribute(k_node<false>, cudaFuncAttributeMaxDynamicSharedMemorySize, node_smem);
    cudaFuncSetAttribute(k_node<true>,  cudaFuncAttributeMaxDynamicSharedMemorySize, node_smem);

    // prolog (counters zeroed by previous call's trailing cleanup; globals start zeroed)
    k_hist_all<<<EBLK+NBLK+SBLK, 256>>>(pos, shifts, eidx, attrs, Wemb);
    k_scans<<<2, 1024>>>();
    k_scatter_all<<<EBLK+NBLK, 256>>>(eidx);
    k_table<<<dim3(TT/TROWS, LLAYERS), 256, TBL_SMEM_BYTES>>>(RW1, RW2, RW3);

    for (int layer=0; layer<LLAYERS; layer++){
        k_up<<<(NN+15)/16, 256, UP_SMEM_BYTES>>>(Wup_s + layer*CC*CC, Wup_v + layer*CC*CC);
        k_edge<<<NBINS, 512>>>(layer);
        if (layer == 0)
            k_node<false><<<dim3(NODE_GX, ZZ), 256, node_smem>>>(
                Wout_s, Wout_v, Wsc_s, Wsc_v, P0, P1, Wprod_s, Wprod_v, out);
        else
            k_node<true><<<dim3(NODE_GX, ZZ), 256, node_smem>>>(
                Wout_s + layer*CC*CC, Wout_v + layer*CC*CC,
                Wsc_s + (size_t)layer*ZZ*CC*CC, Wsc_v + (size_t)layer*ZZ*CC*CC,
                P0 + (size_t)layer*ZZ*CC*3, P1 + (size_t)layer*ZZ*CC*2,
                Wprod_s + layer*CC*CC, Wprod_v + layer*CC*CC,
                out + layer*CC);
    }
    k_cleanup<<<(NBINS+255)/256, 256>>>();
}

// round 17
// speedup vs baseline: 1.0443x; 1.0443x over previous
#include <cuda_runtime.h>
#include <math.h>

#define NN 20000
#define EE 320000
#define CC 64
#define ZZ 10
#define LLAYERS 2
#define HH 64
#define NBES 8
#define TT 1024
#define NBINS (TT-1)

typedef unsigned long long ull;

// ---------------- scratch (device globals; no allocation allowed) ----------------
__device__ float  g_s[NN*CC];
__device__ float  g_v[NN*3*CC];
__device__ float4 g_up[NN*CC];                 // (s_up, vx, vy, vz)
__device__ float4 g_agg[NN*CC];                // (agg0, a1x, a1y, a1z)
__device__ float4 g_tab4[LLAYERS][TT*CC];      // (w00, w110/√3, w011, w101) * 1/32
__device__ float  g_tab1[LLAYERS][TT*CC];      // w111/√2 * 1/32
// unsorted per-edge geometry cache
__device__ int    g_ebinU[EE];
__device__ float4 g_eyfU[EE];
// edge bins (by table row)  -- counters zeroed inside k_table (runs after scatter)
__device__ int    g_bcnt[NBINS];
__device__ int    g_brow[NBINS+1];
__device__ int    g_bwo[NBINS];
__device__ int2   g_esr[EE];                   // (sender, receiver)
__device__ float4 g_eyf[EE];                   // (y0, y1, y2, f)
// node z-sort
__device__ int    g_zcnt[ZZ];
__device__ int    g_zrow[ZZ+1];
__device__ int    g_zwo[ZZ];
__device__ int    g_nid[NN];
__device__ int    g_zU[NN];

__device__ __forceinline__ float silu_f(float x){ return x * (1.0f/(1.0f + __expf(-x))); }

// ---------------- f32x2 helpers ----------------
__device__ __forceinline__ ull pk2(float x){
    ull r; asm("mov.b64 %0, {%1, %1};" : "=l"(r) : "f"(x)); return r;
}
__device__ __forceinline__ void upk(ull p, float& lo, float& hi){
    asm("mov.b64 {%0, %1}, %2;" : "=f"(lo), "=f"(hi) : "l"(p));
}
__device__ __forceinline__ void fma2(ull& d, ull a, ull b){
    asm("fma.rn.f32x2 %0, %1, %2, %0;" : "+l"(d) : "l"(a), "l"(b));
}

// ---------------- fused: edge hist + node z-hist + embedding ----------------
#define EBLK ((EE+255)/256)
#define NBLK ((NN+255)/256)
#define SBLK ((NN*CC+255)/256)

__global__ void k_hist_all(const float* __restrict__ pos, const float* __restrict__ shifts,
                           const int* __restrict__ eidx, const float* __restrict__ attrs,
                           const float* __restrict__ Wemb)
{
    if (blockIdx.x < EBLK) {
        int e = blockIdx.x*blockDim.x + threadIdx.x;
        if (e >= EE) return;
        int snd = eidx[e], rcv = eidx[EE + e];
        float vx = pos[rcv*3+0]-pos[snd*3+0]+shifts[e*3+0];
        float vy = pos[rcv*3+1]-pos[snd*3+1]+shifts[e*3+1];
        float vz = pos[rcv*3+2]-pos[snd*3+2]+shifts[e*3+2];
        float r = sqrtf(vx*vx+vy*vy+vz*vz);
        float u = r * 0.2f;
        if (u >= 1.0f) { g_ebinU[e] = -1; return; }
        float t = u * (float)(TT-1);
        int i0 = (int)t; if (i0 > NBINS-1) i0 = NBINS-1;
        float f = t - (float)i0;
        float inv = 1.0f/(r + 1e-9f);
        const float S3 = 1.7320508075688772f;
        g_ebinU[e] = i0;
        g_eyfU[e]  = make_float4(S3*vx*inv, S3*vy*inv, S3*vz*inv, f);
        atomicAdd(&g_bcnt[i0], 1);
    } else if (blockIdx.x < EBLK + NBLK) {
        int n = (blockIdx.x - EBLK)*blockDim.x + threadIdx.x;
        if (n >= NN) return;
        int z = 0;
        #pragma unroll
        for (int j=0;j<ZZ;j++) if (__ldg(attrs + n*ZZ + j) > 0.5f) z = j;
        g_zU[n] = z;
        atomicAdd(&g_zcnt[z], 1);
    } else {
        int idx = (blockIdx.x - EBLK - NBLK)*blockDim.x + threadIdx.x;
        if (idx >= NN*CC) return;
        int n = idx >> 6, c = idx & 63;
        float acc = 0.f;
        #pragma unroll
        for (int z=0; z<ZZ; z++) acc += __ldg(attrs + n*ZZ + z) * __ldg(Wemb + z*CC + c);
        g_s[idx] = acc;
        g_v[n*192 + c]       = 0.f;
        g_v[n*192 + 64 + c]  = 0.f;
        g_v[n*192 + 128 + c] = 0.f;
    }
}

// ---------------- scans (2 independent blocks) ----------------
__global__ void k_scans()
{
    __shared__ int partial[1024];
    int tid = threadIdx.x;
    if (blockIdx.x == 0) {          // bin scan (NBINS=1023 <= 1024)
        int sum = (tid < NBINS) ? g_bcnt[tid] : 0;
        partial[tid] = sum;
        __syncthreads();
        for (int off=1; off<1024; off<<=1){
            int v = (tid>=off) ? partial[tid-off] : 0;
            __syncthreads();
            partial[tid] += v;
            __syncthreads();
        }
        int run = (tid==0) ? 0 : partial[tid-1];
        if (tid == 1023) g_brow[NBINS] = partial[1023];
        if (tid < NBINS){
            g_brow[tid] = run;
            g_bwo[tid]  = run;
        }
    } else {
        if (tid == 0){
            int run = 0;
            for (int z=0; z<ZZ; z++){
                g_zrow[z] = run; g_zwo[z] = run;
                run += g_zcnt[z];
            }
            g_zrow[ZZ] = run;
        }
    }
}

// ---------------- fused scatter: edges into bin order + nodes into z order ----------------
__global__ void k_scatter_all(const int* __restrict__ eidx)
{
    if (blockIdx.x < EBLK) {
        int e = blockIdx.x*blockDim.x + threadIdx.x;
        if (e >= EE) return;
        int b = g_ebinU[e];
        if (b < 0) return;
        int p = atomicAdd(&g_bwo[b], 1);
        g_esr[p] = make_int2(eidx[e], eidx[EE+e]);
        g_eyf[p] = g_eyfU[e];
    } else {
        int n = (blockIdx.x - EBLK)*blockDim.x + threadIdx.x;
        if (n >= NN) return;
        int p = atomicAdd(&g_zwo[g_zU[n]], 1);
        g_nid[p] = n;
    }
}

// ---------------- radial MLP table: smem weights (float4 staged), 16 rows/block ----------------
// Also zeroes the histogram counters for the next graph replay (runs after scatter).
#define TROWS 16
#define TBL_SMEM_BYTES ((NBES*HH + HH*HH + HH*5*CC + 4*(NBES+HH+HH))*4)

__device__ __forceinline__ void grp_bar(int grp){
    asm volatile("bar.sync %0, 64;" :: "r"(1+grp) : "memory");
}

__global__ __launch_bounds__(256) void k_table(const float* __restrict__ RW1,
                                               const float* __restrict__ RW2,
                                               const float* __restrict__ RW3)
{
    int l = blockIdx.y;
    // fused counter cleanup (safe: k_scatter_all already consumed g_bwo/g_zcnt)
    if (l == 0) {
        int i = blockIdx.x*blockDim.x + threadIdx.x;
        if (i < NBINS) g_bcnt[i] = 0;
        if (i < ZZ)    g_zcnt[i] = 0;
    }
    extern __shared__ float sm[];
    float* sW1 = sm;                      // 512
    float* sW2 = sW1 + NBES*HH;           // 4096
    float* sW3 = sW2 + HH*HH;             // 20480
    float* sFt = sW3 + HH*5*CC;           // 4*8
    float* sH1 = sFt + 4*NBES;            // 4*64
    float* sH2 = sH1 + 4*HH;              // 4*64
    const float4* W1v = (const float4*)(RW1 + l*NBES*HH);
    const float4* W2v = (const float4*)(RW2 + l*HH*HH);
    const float4* W3v = (const float4*)(RW3 + l*HH*5*CC);
    int tid = threadIdx.x;
    for (int i=tid;i<(NBES*HH)/4;i+=256) ((float4*)sW1)[i]=__ldg(W1v+i);
    for (int i=tid;i<(HH*HH)/4;  i+=256) ((float4*)sW2)[i]=__ldg(W2v+i);
    for (int i=tid;i<(HH*5*CC)/4;i+=256) ((float4*)sW3)[i]=__ldg(W3v+i);
    __syncthreads();

    int grp = tid >> 6;      // 0..3 (independent row pipelines)
    int gt  = tid & 63;      // channel within group
    const float PI = 3.14159265358979323846f;
    const float IA  = 1.0f/32.0f;
    const float IS3 = 0.5773502691896258f;
    const float IS2 = 0.7071067811865475f;

    for (int r = grp; r < TROWS; r += 4) {
        int i = blockIdx.x*TROWS + r;
        if (gt < NBES) {
            float u = (float)i / (float)(TT-1);
            float rr = 5.0f*u;
            float inv = 1.0f/(rr + 1e-9f);
            float env = 0.0f;
            if (u < 1.0f) {
                float u2=u*u, u4=u2*u2, u6=u4*u2;
                env = 1.0f - 28.0f*u6 + 48.0f*u6*u - 21.0f*u6*u2;
            }
            float pref = 0.6324555320336759f * inv * env;
            sFt[grp*NBES + gt] = pref * sinf((float)(gt+1) * PI * u);
        }
        grp_bar(grp);
        {
            float a = 0.f;
            #pragma unroll
            for (int k=0;k<NBES;k++) a += sFt[grp*NBES+k]*sW1[k*HH+gt];
            sH1[grp*HH+gt] = silu_f(a);
        }
        grp_bar(grp);
        {
            float a = 0.f;
            #pragma unroll 8
            for (int d=0;d<HH;d++) a += sH1[grp*HH+d]*sW2[d*HH+gt];
            sH2[grp*HH+gt] = silu_f(a);
        }
        grp_bar(grp);
        {
            float o[5] = {};
            #pragma unroll 8
            for (int d=0;d<HH;d++){
                float h = sH2[grp*HH+d];
                #pragma unroll
                for (int g=0;g<5;g++) o[g] += h*sW3[d*320 + g*64 + gt];
            }
            g_tab4[l][i*64 + gt] = make_float4(o[0]*IA, o[1]*IA*IS3, o[2]*IA, o[3]*IA);
            g_tab1[l][i*64 + gt] = o[4]*IA*IS2;
        }
        grp_bar(grp);
    }
}

// ---------------- s_up / v_up: f32x2 packed, paired weights, 2 nodes/warp + agg zero ----------------
#define UP_SMEM_BYTES (2*CC*CC*4 + 8*2*CC*16)

__global__ __launch_bounds__(256) void k_up(const float* __restrict__ Ws, const float* __restrict__ Wv)
{
    extern __shared__ float sm[];
    float*  sWs = sm;
    float*  sWv = sm + 4096;
    float4* stage = (float4*)(sm + 8192);
    int tid = threadIdx.x;
    // paired layout: channel pair (l, l+32) adjacent
    for (int i=tid;i<4096;i+=256){
        int c = i>>6, l = i&63;
        int dst = (c<<6) | ((l<32) ? (l<<1) : (((l-32)<<1)|1));
        sWs[dst]=Ws[i]; sWv[dst]=Wv[i];
    }
    __syncthreads();
    int warp = tid>>5, lane = tid&31;
    int n0 = (blockIdx.x*8 + warp)*2;
    if (n0 >= NN) return;
    int nk = (n0+1 < NN) ? 2 : 1;
    float4* st = stage + warp*2*CC;
    const ull* ws8 = (const ull*)sWs;
    const ull* wv8 = (const ull*)sWv;
    float4 z4 = make_float4(0.f,0.f,0.f,0.f);
    for (int t=0;t<nk;t++){
        int n = n0 + t;
        st[t*CC+lane]    = make_float4(g_s[n*64+lane],
                                       g_v[n*192+lane], g_v[n*192+64+lane], g_v[n*192+128+lane]);
        st[t*CC+lane+32] = make_float4(g_s[n*64+lane+32],
                                       g_v[n*192+lane+32], g_v[n*192+64+lane+32], g_v[n*192+128+lane+32]);
        g_agg[n*64+lane]    = z4;
        g_agg[n*64+lane+32] = z4;
    }
    if (nk < 2){ st[CC+lane]=z4; st[CC+lane+32]=z4; }
    __syncwarp();
    ull as[2]={0,0}, av[2][3]={{0,0,0},{0,0,0}};
    #pragma unroll 4
    for (int c=0;c<CC;c++){
        int wi = (c<<5) + lane;
        ull ws = ws8[wi], wv = wv8[wi];
        #pragma unroll
        for (int t=0;t<2;t++){
            float4 sv = st[t*CC+c];
            fma2(as[t],    pk2(sv.x), ws);
            fma2(av[t][0], pk2(sv.y), wv);
            fma2(av[t][1], pk2(sv.z), wv);
            fma2(av[t][2], pk2(sv.w), wv);
        }
    }
    for (int t=0;t<nk;t++){
        int n = n0 + t;
        float a0,a1, x0,x1, y0,y1, zz0,zz1;
        upk(as[t], a0, a1);
        upk(av[t][0], x0, x1);
        upk(av[t][1], y0, y1);
        upk(av[t][2], zz0, zz1);
        g_up[n*64+lane]    = make_float4(a0, x0, y0, zz0);
        g_up[n*64+lane+32] = make_float4(a1, x1, y1, zz1);
    }
}

// ---------------- edge kernel: block per u-bin, 16 warps, 2-edge ILP (R15-proven) ----------------
__device__ __forceinline__ void edge_emit(int rcv, float4 yf, float4 up, int c,
    const float4* sA4, const float4* sD4, const float* sA1, const float* sD1)
{
    float f = yf.w;
    float4 a4 = sA4[c], d4 = sD4[c];
    float w0 = fmaf(f, d4.x, a4.x);
    float w1 = fmaf(f, d4.y, a4.y);
    float w2 = fmaf(f, d4.z, a4.z);
    float w3 = fmaf(f, d4.w, a4.w);
    float w4 = fmaf(f, sD1[c], sA1[c]);
    float dv = up.y*yf.x + up.z*yf.y + up.w*yf.z;
    float m0 = w0*up.x + w1*dv;
    float cx = up.z*yf.z - up.w*yf.y;
    float cy = up.w*yf.x - up.y*yf.z;
    float cz = up.y*yf.y - up.z*yf.x;
    float sy = w2*up.x;
    float m1x = sy*yf.x + w3*up.y + w4*cx;
    float m1y = sy*yf.y + w3*up.z + w4*cy;
    float m1z = sy*yf.z + w3*up.w + w4*cz;
    float* p = (float*)(g_agg + rcv*64 + c);
    asm volatile("red.global.add.v4.f32 [%0], {%1,%2,%3,%4};"
                 :: "l"(p), "f"(m0), "f"(m1x), "f"(m1y), "f"(m1z) : "memory");
}

__global__ __launch_bounds__(512) void k_edge(int layer)
{
    __shared__ float4 sA4[CC], sD4[CC];
    __shared__ float  sA1[CC], sD1[CC];
    int bin = blockIdx.x;
    int s0 = __ldg(&g_brow[bin]);
    int s1 = __ldg(&g_brow[bin+1]);
    if (s0 == s1) return;
    int tid = threadIdx.x;
    if (tid < CC) {
        float4 a4 = g_tab4[layer][bin*CC + tid];
        float4 b4 = g_tab4[layer][(bin+1)*CC + tid];
        sA4[tid] = a4;
        sD4[tid] = make_float4(b4.x-a4.x, b4.y-a4.y, b4.z-a4.z, b4.w-a4.w);
        float a1 = g_tab1[layer][bin*CC + tid];
        float b1 = g_tab1[layer][(bin+1)*CC + tid];
        sA1[tid] = a1; sD1[tid] = b1 - a1;
    }
    __syncthreads();
    int warp = tid>>5, lane = tid&31;

    for (int j = s0 + warp*2; j < s1; j += 32) {
        int2   srA = __ldg(&g_esr[j]);
        float4 yfA = __ldg(&g_eyf[j]);
        bool hasB = (j+1 < s1);
        int2 srB; float4 yfB;
        float4 upB0, upB1;
        float4 upA0 = __ldg(&g_up[srA.x*64 + lane]);
        float4 upA1 = __ldg(&g_up[srA.x*64 + lane + 32]);
        if (hasB) {
            srB = __ldg(&g_esr[j+1]);
            yfB = __ldg(&g_eyf[j+1]);
            upB0 = __ldg(&g_up[srB.x*64 + lane]);
            upB1 = __ldg(&g_up[srB.x*64 + lane + 32]);
        }
        edge_emit(srA.y, yfA, upA0, lane,      sA4, sD4, sA1, sD1);
        edge_emit(srA.y, yfA, upA1, lane + 32, sA4, sD4, sA1, sD1);
        if (hasB) {
            edge_emit(srB.y, yfB, upB0, lane,      sA4, sD4, sA1, sD1);
            edge_emit(srB.y, yfB, upB1, lane + 32, sA4, sD4, sA1, sD1);
        }
    }
}

// ---------------- node update: f32x2 packed math; LAST skips dead v-path ----------------
#define NODE_SMEM_FLOATS (6*CC*CC + 8*3*CC*4)
#define NODE_GX 32

template<bool LAST>
__global__ __launch_bounds__(256) void k_node(
    const float* __restrict__ Wout_s, const float* __restrict__ Wout_v,
    const float* __restrict__ Wsc_sL, const float* __restrict__ Wsc_vL,
    const float* __restrict__ P0L,    const float* __restrict__ P1L,
    const float* __restrict__ Wprod_s,const float* __restrict__ Wprod_v,
    float* __restrict__ outL)
{
    int z  = blockIdx.y;
    int s0 = g_zrow[z];
    int s1 = g_zrow[z+1];
    if (s0 + (int)blockIdx.x*8 >= s1) return;

    extern __shared__ float sm[];
    float* sWos = sm;
    float* sWov = sWos + 4096;
    float* sWss = sWov + 4096;
    float* sWsv = sWss + 4096;
    float* sWps = sWsv + 4096;
    float* sWpv = sWps + 4096;
    float4* stage = (float4*)(sm + 6*4096);
    int tid = threadIdx.x;
    const float* Wss_g = Wsc_sL + (size_t)z*4096;
    const float* Wsv_g = Wsc_vL + (size_t)z*4096;
    for (int i=tid;i<4096;i+=blockDim.x){
        int c = i>>6, l = i&63;
        int dst = (c<<6) | ((l<32) ? (l<<1) : (((l-32)<<1)|1));
        sWos[dst]=Wout_s[i]; sWov[dst]=Wout_v[i];
        sWss[dst]=__ldg(Wss_g+i);
        sWps[dst]=Wprod_s[i];
        if (!LAST){ sWsv[dst]=__ldg(Wsv_g+i); sWpv[dst]=Wprod_v[i]; }
    }
    __syncthreads();
    int warp = tid>>5, lane = tid&31;
    float4* stA = stage + warp*3*CC;   // agg  [64]
    float4* stS = stA + CC;            // (s, v) [64]
    float4* stP = stS + CC;            // prod [64]
    const ull* wos8 = (const ull*)sWos;
    const ull* wov8 = (const ull*)sWov;
    const ull* wss8 = (const ull*)sWss;
    const ull* wsv8 = (const ull*)sWsv;
    const ull* wps8 = (const ull*)sWps;
    const ull* wpv8 = (const ull*)sWpv;

    const float* p0  = P0L + (size_t)z*CC*3;
    const float* q0  = P1L + (size_t)z*CC*2;
    float pa0=__ldg(p0+lane*3+0), pa1=__ldg(p0+lane*3+1), pa2=__ldg(p0+lane*3+2);
    float pb0=__ldg(p0+(lane+32)*3+0), pb1=__ldg(p0+(lane+32)*3+1), pb2=__ldg(p0+(lane+32)*3+2);
    float qa0=__ldg(q0+lane*2+0), qa1=__ldg(q0+lane*2+1);
    float qb0=__ldg(q0+(lane+32)*2+0), qb1=__ldg(q0+(lane+32)*2+1);

    for (int idx = s0 + blockIdx.x*8 + warp; idx < s1; idx += NODE_GX*8) {
        int n = __ldg(&g_nid[idx]);

        stA[lane]    = g_agg[n*64+lane];
        stA[lane+32] = g_agg[n*64+lane+32];
        stS[lane]    = make_float4(g_s[n*64+lane],
                                   g_v[n*192+lane], g_v[n*192+64+lane], g_v[n*192+128+lane]);
        stS[lane+32] = make_float4(g_s[n*64+lane+32],
                                   g_v[n*192+lane+32], g_v[n*192+64+lane+32], g_v[n*192+128+lane+32]);
        __syncwarp();

        ull ms = 0, scs = 0;
        ull mv0=0, mv1=0, mv2=0, scv0=0, scv1=0, scv2=0;
        #pragma unroll 4
        for (int c=0;c<CC;c++){
            float4 A = stA[c];
            float4 S = stS[c];
            int wi = (c<<5) + lane;
            fma2(ms,  pk2(A.x), wos8[wi]);
            fma2(scs, pk2(S.x), wss8[wi]);
            ull wov = wov8[wi];
            fma2(mv0, pk2(A.y), wov);
            fma2(mv1, pk2(A.z), wov);
            fma2(mv2, pk2(A.w), wov);
            if (!LAST){
                ull wsv = wsv8[wi];
                fma2(scv0, pk2(S.y), wsv);
                fma2(scv1, pk2(S.z), wsv);
                fma2(scv2, pk2(S.w), wsv);
            }
        }

        float ms0, ms1, mvx0,mvx1, mvy0,mvy1, mvz0,mvz1;
        upk(ms, ms0, ms1);
        upk(mv0, mvx0, mvx1);
        upk(mv1, mvy0, mvy1);
        upk(mv2, mvz0, mvz1);

        float n2a = mvx0*mvx0 + mvy0*mvy0 + mvz0*mvz0;
        float n2b = mvx1*mvx1 + mvy1*mvy1 + mvz1*mvz1;
        float ga = qa0 + qa1*ms0;
        float gb = qb0 + qb1*ms1;
        stP[lane]    = make_float4(pa0*ms0 + pa1*ms0*ms0 + pa2*n2a, ga*mvx0, ga*mvy0, ga*mvz0);
        stP[lane+32] = make_float4(pb0*ms1 + pb1*ms1*ms1 + pb2*n2b, gb*mvx1, gb*mvy1, gb*mvz1);
        __syncwarp();

        ull sn = scs, vn0 = scv0, vn1 = scv1, vn2 = scv2;
        #pragma unroll 4
        for (int c=0;c<CC;c++){
            float4 P = stP[c];
            int wi = (c<<5) + lane;
            fma2(sn,  pk2(P.x), wps8[wi]);
            if (!LAST){
                ull wpv = wpv8[wi];
                fma2(vn0, pk2(P.y), wpv);
                fma2(vn1, pk2(P.z), wpv);
                fma2(vn2, pk2(P.w), wpv);
            }
        }

        float sn0,sn1;
        upk(sn, sn0, sn1);
        if (!LAST){
            float vx0,vx1, vy0,vy1, vz0,vz1;
            upk(vn0, vx0, vx1);
            upk(vn1, vy0, vy1);
            upk(vn2, vz0, vz1);
            g_s[n*64+lane]=sn0; g_s[n*64+lane+32]=sn1;
            g_v[n*192+lane]=vx0;      g_v[n*192+lane+32]=vx1;
            g_v[n*192+64+lane]=vy0;   g_v[n*192+64+lane+32]=vy1;
            g_v[n*192+128+lane]=vz0;  g_v[n*192+128+lane+32]=vz1;
        }
        outL[n*128+lane]=sn0; outL[n*128+lane+32]=sn1;
        __syncwarp();
    }
}

// ---------------- launch ----------------
extern "C" void kernel_launch(void* const* d_in, const int* in_sizes, int n_in,
                              void* d_out, int out_size)
{
    const float* attrs   = (const float*)d_in[0];
    const float* pos     = (const float*)d_in[1];
    const float* shifts  = (const float*)d_in[2];
    const float* Wemb    = (const float*)d_in[3];
    const float* Wup_s   = (const float*)d_in[4];
    const float* Wup_v   = (const float*)d_in[5];
    const float* RW1     = (const float*)d_in[6];
    const float* RW2     = (const float*)d_in[7];
    const float* RW3     = (const float*)d_in[8];
    const float* Wout_s  = (const float*)d_in[9];
    const float* Wout_v  = (const float*)d_in[10];
    const float* Wsc_s   = (const float*)d_in[11];
    const float* Wsc_v   = (const float*)d_in[12];
    const float* P0      = (const float*)d_in[13];
    const float* P1      = (const float*)d_in[14];
    const float* Wprod_s = (const float*)d_in[15];
    const float* Wprod_v = (const float*)d_in[16];
    const int*   eidx    = (const int*)d_in[17];
    float* out = (float*)d_out;

    const int node_smem = NODE_SMEM_FLOATS * 4;
    cudaFuncSetAttribute(k_up, cudaFuncAttributeMaxDynamicSharedMemorySize, UP_SMEM_BYTES);
    cudaFuncSetAttribute(k_table, cudaFuncAttributeMaxDynamicSharedMemorySize, TBL_SMEM_BYTES);
    cudaFuncSetAttribute(k_node<false>, cudaFuncAttributeMaxDynamicSharedMemorySize, node_smem);
    cudaFuncSetAttribute(k_node<true>,  cudaFuncAttributeMaxDynamicSharedMemorySize, node_smem);

    // prolog (counters zeroed by previous call's k_table; globals start zeroed at load)
    k_hist_all<<<EBLK+NBLK+SBLK, 256>>>(pos, shifts, eidx, attrs, Wemb);
    k_scans<<<2, 1024>>>();
    k_scatter_all<<<EBLK+NBLK, 256>>>(eidx);
    k_table<<<dim3(TT/TROWS, LLAYERS), 256, TBL_SMEM_BYTES>>>(RW1, RW2, RW3);

    for (int layer=0; layer<LLAYERS; layer++){
        k_up<<<(NN+15)/16, 256, UP_SMEM_BYTES>>>(Wup_s + layer*CC*CC, Wup_v + layer*CC*CC);
        k_edge<<<NBINS, 512>>>(layer);
        if (layer == 0)
            k_node<false><<<dim3(NODE_GX, ZZ), 256, node_smem>>>(
                Wout_s, Wout_v, Wsc_s, Wsc_v, P0, P1, Wprod_s, Wprod_v, out);
        else
            k_node<true><<<dim3(NODE_GX, ZZ), 256, node_smem>>>(
                Wout_s + layer*CC*CC, Wout_v + layer*CC*CC,
                Wsc_s + (size_t)layer*ZZ*CC*CC, Wsc_v + (size_t)layer*ZZ*CC*CC,
                P0 + (size_t)layer*ZZ*CC*3, P1 + (size_t)layer*ZZ*CC*2,
                Wprod_s + layer*CC*CC, Wprod_v + layer*CC*CC,
                out + layer*CC);
    }
}